// round 12
// baseline (speedup 1.0000x reference)
#include <cuda_runtime.h>
#include <cuda_fp16.h>
#include <cstdint>

#define NN 50000
#define EE 800000
#define DD 128
#define HH 4
#define NB 49          // scan blocks per array: 49*1024 >= NN
#define ROWT 391       // (NN+127)/128
#define CONVB 512      // convert blocks inside the fused proj launch

// ---- scratch (device globals; no allocation allowed) ----
__device__ unsigned g_Kh[NN * 64];   // K rows as 64 half2 (fp16)
__device__ unsigned g_Mh[NN * 64];   // M rows as 64 half2 (fp16)
__device__ float g_Q[NN * DD];
__device__ float g_ev[EE * HH];      // also reused as int scratch pre-pass1
__device__ float g_rnorm[NN * HH];
__device__ float g_out[NN * DD];
__device__ float g_h[NN * DD];
__device__ float g_colsum[DD];
__device__ float g_colsumsq[DD];
__device__ float g_scale[DD];
__device__ float g_shift[DD];
__device__ int   g_is64;
__device__ int   g_ctr;
__device__ int   g_c1, g_c2;
__device__ int   g_flag1, g_flag2;

// CSR structures
__device__ int  g_deg_s[NN];
__device__ int  g_deg_d[NN];
__device__ int  g_off_s[NN + 1];
__device__ int  g_off_d[NN + 1];
__device__ int  g_cur_s[NN];     // also inclusive-scan temp
__device__ int  g_cur_d[NN];
__device__ int  g_bsum[2][64];
__device__ int  g_csr_s_dst[EE];     // dst per src-sorted slot
__device__ int2 g_csr_d[EE];         // (src, src_slot) per dst-sorted slot

// =======================================================================
// init + dtype probe. Reference asks int64 but JAX x64-disabled silently
// yields int32; first-2048-u64 all < NN only if genuinely int64.
// =======================================================================
__global__ void k_init(const unsigned long long* __restrict__ p)
{
    int i = blockIdx.x * blockDim.x + threadIdx.x;
    int stride = gridDim.x * blockDim.x;
    for (int j = i; j < NN; j += stride) { g_deg_s[j] = 0; g_deg_d[j] = 0; }
    if (i < DD) { g_colsum[i] = 0.f; g_colsumsq[i] = 0.f; }
    if (i == 0) { g_ctr = 0; g_c1 = 0; g_c2 = 0; g_flag1 = 0; g_flag2 = 0; }
    if (blockIdx.x == 0) {
        __shared__ int ok;
        if (threadIdx.x == 0) ok = 1;
        __syncthreads();
        bool bad = false;
#pragma unroll
        for (int j = 0; j < 8; j++)
            if (p[threadIdx.x * 8 + j] >= (unsigned long long)NN) bad = true;
        if (bad) atomicExch(&ok, 0);
        __syncthreads();
        if (threadIdx.x == 0) g_is64 = ok;
    }
}

// =======================================================================
// tf32 tensor-core GEMM: 128x128 tile, BK=32, m16n8k8, dynamic smem.
// BN=false: cp.async double-buffered (fp32 staged raw, cvt after LDS).
// BN=true : synchronous path with fused BatchNorm+ReLU on A load.
// STATS   : per-column sum/sumsq of output + last-block BN finalize.
// HOUT    : emit fp16 (half2-packed) output rows instead of fp32.
// =======================================================================
#define AS_STRIDE 36
#define WS_STRIDE 136
#define STGW (128 * AS_STRIDE + 32 * WS_STRIDE)              // words per stage
#define DSMEM (2 * STGW * 4 + 4 * 128 * 8)                   // 75776 B

__device__ __forceinline__ uint32_t f2tf(float x)
{
    uint32_t r;
    asm("cvt.rna.tf32.f32 %0, %1;" : "=r"(r) : "f"(x));
    return r;
}

__device__ __forceinline__ void mma_tf32(float* c, const uint32_t* a, const uint32_t* b)
{
    asm volatile(
        "mma.sync.aligned.m16n8k8.row.col.f32.tf32.tf32.f32 "
        "{%0,%1,%2,%3}, {%4,%5,%6,%7}, {%8,%9}, {%0,%1,%2,%3};"
        : "+f"(c[0]), "+f"(c[1]), "+f"(c[2]), "+f"(c[3])
        : "r"(a[0]), "r"(a[1]), "r"(a[2]), "r"(a[3]), "r"(b[0]), "r"(b[1]));
}

__device__ __forceinline__ void cp16(uint32_t saddr, const void* gptr, int szbytes)
{
    asm volatile("cp.async.cg.shared.global [%0], [%1], 16, %2;"
                 :: "r"(saddr), "l"(gptr), "r"(szbytes));
}

template <bool CVT>
__device__ __forceinline__ void gemm_compute(
    const uint32_t* __restrict__ As, const uint32_t* __restrict__ Ws,
    float acc[2][8][4], int warpM, int warpN, int g, int q)
{
#pragma unroll
    for (int ks = 0; ks < 4; ks++) {
        const int k = ks * 8;
        uint32_t a[2][4];
#pragma unroll
        for (int mt = 0; mt < 2; mt++) {
            int Rm = warpM * 32 + mt * 16;
            uint32_t r0 = As[(Rm + g)     * AS_STRIDE + k + q];
            uint32_t r1 = As[(Rm + g + 8) * AS_STRIDE + k + q];
            uint32_t r2 = As[(Rm + g)     * AS_STRIDE + k + q + 4];
            uint32_t r3 = As[(Rm + g + 8) * AS_STRIDE + k + q + 4];
            if (CVT) {
                r0 = f2tf(__uint_as_float(r0));
                r1 = f2tf(__uint_as_float(r1));
                r2 = f2tf(__uint_as_float(r2));
                r3 = f2tf(__uint_as_float(r3));
            }
            a[mt][0] = r0; a[mt][1] = r1; a[mt][2] = r2; a[mt][3] = r3;
        }
        uint32_t b[8][2];
#pragma unroll
        for (int nt = 0; nt < 8; nt++) {
            int col = warpN * 64 + nt * 8 + g;
            uint32_t b0 = Ws[(k + q)     * WS_STRIDE + col];
            uint32_t b1 = Ws[(k + q + 4) * WS_STRIDE + col];
            if (CVT) { b0 = f2tf(__uint_as_float(b0)); b1 = f2tf(__uint_as_float(b1)); }
            b[nt][0] = b0; b[nt][1] = b1;
        }
#pragma unroll
        for (int mt = 0; mt < 2; mt++)
#pragma unroll
            for (int nt = 0; nt < 8; nt++)
                mma_tf32(acc[mt][nt], a[mt], b[nt]);
    }
}

template <bool BN, bool STATS, bool HOUT>
__device__ __forceinline__ void gemm_body(
    int rowBase,
    const float* __restrict__ A, const float* __restrict__ W,
    const float* __restrict__ bias, float* __restrict__ C,
    unsigned* __restrict__ Ch, float outScale,
    const float* __restrict__ gamma, const float* __restrict__ beta,
    int nblocks)
{
    extern __shared__ uint32_t dyn[];
    float2* red = (float2*)(dyn + 2 * STGW);

    const int tid = threadIdx.x;
    const int wid = tid >> 5;
    const int lane = tid & 31;
    const int g = lane >> 2;
    const int q = lane & 3;
    const int warpM = wid & 3;
    const int warpN = wid >> 2;

    float acc[2][8][4];
#pragma unroll
    for (int mt = 0; mt < 2; mt++)
#pragma unroll
        for (int nt = 0; nt < 8; nt++)
#pragma unroll
            for (int r = 0; r < 4; r++) acc[mt][nt][r] = 0.f;

    if (!BN) {
        // ---------- cp.async double-buffered path ----------
        const uint32_t sbase = (uint32_t)__cvta_generic_to_shared(dyn);
        // prologue: stage 0 (kc = 0)
        {
#pragma unroll
            for (int it = 0; it < 4; it++) {
                int idx = tid + it * 256;
                int r = idx >> 3, c4 = idx & 7;
                int grow = rowBase + r;
                int cg = grow < NN ? grow : NN - 1;
                cp16(sbase + (r * AS_STRIDE + c4 * 4) * 4,
                     A + (size_t)cg * DD + c4 * 4, grow < NN ? 16 : 0);
            }
#pragma unroll
            for (int it = 0; it < 4; it++) {
                int idx = tid + it * 256;
                int r = idx >> 5, c4 = idx & 31;
                cp16(sbase + (128 * AS_STRIDE + r * WS_STRIDE + c4 * 4) * 4,
                     W + (size_t)r * DD + c4 * 4, 16);
            }
            asm volatile("cp.async.commit_group;");
        }
#pragma unroll
        for (int kcIdx = 0; kcIdx < 4; kcIdx++) {
            if (kcIdx < 3) {
                int kc = (kcIdx + 1) * 32;
                uint32_t soff = sbase + ((kcIdx + 1) & 1) * STGW * 4;
#pragma unroll
                for (int it = 0; it < 4; it++) {
                    int idx = tid + it * 256;
                    int r = idx >> 3, c4 = idx & 7;
                    int grow = rowBase + r;
                    int cg = grow < NN ? grow : NN - 1;
                    cp16(soff + (r * AS_STRIDE + c4 * 4) * 4,
                         A + (size_t)cg * DD + kc + c4 * 4, grow < NN ? 16 : 0);
                }
#pragma unroll
                for (int it = 0; it < 4; it++) {
                    int idx = tid + it * 256;
                    int r = idx >> 5, c4 = idx & 31;
                    cp16(soff + (128 * AS_STRIDE + r * WS_STRIDE + c4 * 4) * 4,
                         W + (size_t)(kc + r) * DD + c4 * 4, 16);
                }
                asm volatile("cp.async.commit_group;");
                asm volatile("cp.async.wait_group 1;");
            } else {
                asm volatile("cp.async.wait_group 0;");
            }
            __syncthreads();
            const uint32_t* stg = dyn + (kcIdx & 1) * STGW;
            gemm_compute<true>(stg, stg + 128 * AS_STRIDE, acc, warpM, warpN, g, q);
            __syncthreads();
        }
    } else {
        // ---------- synchronous path with fused BN+ReLU ----------
        uint32_t* As = dyn;
        uint32_t* Ws = dyn + 128 * AS_STRIDE;
        for (int kc = 0; kc < DD; kc += 32) {
#pragma unroll
            for (int it = 0; it < 4; it++) {
                int idx = tid + it * 256;
                int r = idx >> 3, c4 = idx & 7;
                int grow = rowBase + r;
                float4 v = make_float4(0.f, 0.f, 0.f, 0.f);
                if (grow < NN) v = *(const float4*)(A + (size_t)grow * DD + kc + c4 * 4);
                int cb = kc + c4 * 4;
                v.x = fmaxf(v.x * g_scale[cb + 0] + g_shift[cb + 0], 0.f);
                v.y = fmaxf(v.y * g_scale[cb + 1] + g_shift[cb + 1], 0.f);
                v.z = fmaxf(v.z * g_scale[cb + 2] + g_shift[cb + 2], 0.f);
                v.w = fmaxf(v.w * g_scale[cb + 3] + g_shift[cb + 3], 0.f);
                uint4 t = make_uint4(f2tf(v.x), f2tf(v.y), f2tf(v.z), f2tf(v.w));
                *(uint4*)&As[r * AS_STRIDE + c4 * 4] = t;
            }
#pragma unroll
            for (int it = 0; it < 4; it++) {
                int idx = tid + it * 256;
                int r = idx >> 5, c4 = idx & 31;
                float4 v = *(const float4*)(W + (size_t)(kc + r) * DD + c4 * 4);
                uint4 t = make_uint4(f2tf(v.x), f2tf(v.y), f2tf(v.z), f2tf(v.w));
                *(uint4*)&Ws[r * WS_STRIDE + c4 * 4] = t;
            }
            __syncthreads();
            gemm_compute<false>(As, Ws, acc, warpM, warpN, g, q);
            __syncthreads();
        }
    }

    // ---------- epilogue ----------
#pragma unroll
    for (int nt = 0; nt < 8; nt++) {
        int col = warpN * 64 + nt * 8 + 2 * q;
        float bb0 = bias[col], bb1 = bias[col + 1];
        float cs0 = 0.f, cs1 = 0.f, cq0 = 0.f, cq1 = 0.f;
#pragma unroll
        for (int mt = 0; mt < 2; mt++) {
            int r0 = rowBase + warpM * 32 + mt * 16 + g;
            if (r0 < NN) {
                float o0 = (acc[mt][nt][0] + bb0) * outScale;
                float o1 = (acc[mt][nt][1] + bb1) * outScale;
                if (HOUT) {
                    __half2 hh = __floats2half2_rn(o0, o1);
                    Ch[(size_t)r0 * 64 + (col >> 1)] = *(unsigned*)&hh;
                } else {
                    *(float2*)(C + (size_t)r0 * DD + col) = make_float2(o0, o1);
                }
                if (STATS) { cs0 += o0; cq0 += o0 * o0; cs1 += o1; cq1 += o1 * o1; }
            }
            int r1 = r0 + 8;
            if (r1 < NN) {
                float o2 = (acc[mt][nt][2] + bb0) * outScale;
                float o3 = (acc[mt][nt][3] + bb1) * outScale;
                if (HOUT) {
                    __half2 hh = __floats2half2_rn(o2, o3);
                    Ch[(size_t)r1 * 64 + (col >> 1)] = *(unsigned*)&hh;
                } else {
                    *(float2*)(C + (size_t)r1 * DD + col) = make_float2(o2, o3);
                }
                if (STATS) { cs0 += o2; cq0 += o2 * o2; cs1 += o3; cq1 += o3 * o3; }
            }
        }
        if (STATS) {
#pragma unroll
            for (int mask = 4; mask <= 16; mask <<= 1) {
                cs0 += __shfl_xor_sync(0xffffffffu, cs0, mask);
                cq0 += __shfl_xor_sync(0xffffffffu, cq0, mask);
                cs1 += __shfl_xor_sync(0xffffffffu, cs1, mask);
                cq1 += __shfl_xor_sync(0xffffffffu, cq1, mask);
            }
            if (g == 0) {
                red[warpM * 128 + col]     = make_float2(cs0, cq0);
                red[warpM * 128 + col + 1] = make_float2(cs1, cq1);
            }
        }
    }

    if (STATS) {
        __syncthreads();
        if (tid < 128) {
            float a = 0.f, b = 0.f;
#pragma unroll
            for (int r = 0; r < 4; r++) {
                float2 v = red[r * 128 + tid];
                a += v.x; b += v.y;
            }
            atomicAdd(&g_colsum[tid], a);
            atomicAdd(&g_colsumsq[tid], b);
        }
        __threadfence();
        __syncthreads();
        __shared__ int amLast;
        if (tid == 0)
            amLast = (atomicAdd(&g_ctr, 1) == nblocks - 1);
        __syncthreads();
        if (amLast && tid < 128) {
            int c = tid;
            float invN = 1.0f / (float)NN;
            float mean = g_colsum[c] * invN;
            float var  = g_colsumsq[c] * invN - mean * mean;
            float rstd = rsqrtf(var + 1e-5f);
            float sc = rstd * gamma[c];
            g_scale[c] = sc;
            g_shift[c] = beta[c] - mean * sc;
        }
    }
}

// =======================================================================
// fused launch: blocks [0, CONVB) run edge-index convert + histograms,
// blocks [CONVB, CONVB+3*ROWT) run the 3 projection GEMMs.
// K and M are emitted as fp16 (gather operands); Q stays fp32.
// =======================================================================
__global__ void __launch_bounds__(256, 2) k_proj_convert(
    const float* __restrict__ x,
    const float* __restrict__ Wk, const float* __restrict__ bk,
    const float* __restrict__ Wm, const float* __restrict__ bm,
    const float* __restrict__ Wq, const float* __restrict__ bq,
    const void* __restrict__ raw,
    int* __restrict__ srcA, int* __restrict__ dstA)
{
    if (blockIdx.x < CONVB) {
        const long long* e64 = (const long long*)raw;
        const int*       e32 = (const int*)raw;
        const int is64 = g_is64;
        int i = blockIdx.x * 256 + threadIdx.x;
        int stride = CONVB * 256;
        for (int e = i; e < EE; e += stride) {
            int s, d;
            if (is64) { s = (int)e64[e]; d = (int)e64[EE + e]; }
            else      { s = e32[e];      d = e32[EE + e]; }
            srcA[e] = s; dstA[e] = d;
            atomicAdd(&g_deg_s[s], 1);
            atomicAdd(&g_deg_d[d], 1);
        }
    } else {
        int gb = blockIdx.x - CONVB;
        int by = gb / ROWT;
        int bx = gb - by * ROWT;
        if (by == 0)
            gemm_body<false, false, true>(bx * 128, x, Wk, bk, nullptr, g_Kh, 1.f,
                                          nullptr, nullptr, 0);
        else if (by == 1)
            gemm_body<false, false, true>(bx * 128, x, Wm, bm, nullptr, g_Mh, 1.f,
                                          nullptr, nullptr, 0);
        else
            gemm_body<false, false, false>(bx * 128, x, Wq, bq, g_Q, nullptr,
                                           0.17677669529663687f, nullptr, nullptr, 0); // 1/sqrt(32)
    }
}

__global__ void __launch_bounds__(256, 2) k_gemm_mlp1(
    const float* __restrict__ W1, const float* __restrict__ b1,
    const float* __restrict__ gamma, const float* __restrict__ beta)
{
    gemm_body<false, true, false>(blockIdx.x * 128, g_out, W1, b1, g_h, nullptr,
                                  1.f, gamma, beta, ROWT);
}

__global__ void __launch_bounds__(256, 2) k_gemm_mlp2(
    const float* __restrict__ W2, const float* __restrict__ b2,
    float* __restrict__ outp)
{
    gemm_body<true, false, false>(blockIdx.x * 128, g_h, W2, b2, outp, nullptr,
                                  1.f, nullptr, nullptr, 0);
}

// =======================================================================
// fused CSR build: block-scan (phase 1) -> spin -> offsets (phase 2)
// -> spin -> scatter (phase 3). 98 resident blocks; two flag barriers.
// =======================================================================
__global__ void __launch_bounds__(1024) k_build(
    const int* __restrict__ srcA, const int* __restrict__ dstA)
{
    const int a = blockIdx.y;
    const int bx = blockIdx.x;
    const int t = threadIdx.x;
    const int* deg = a ? g_deg_d : g_deg_s;
    int* tmp = a ? g_cur_d : g_cur_s;
    int* off = a ? g_off_d : g_off_s;
    __shared__ int s[1024];
    __shared__ int amLast;

    // phase 1: block inclusive scan
    int i = bx * 1024 + t;
    int v = (i < NN) ? deg[i] : 0;
    s[t] = v;
    __syncthreads();
#pragma unroll
    for (int d = 1; d < 1024; d <<= 1) {
        int u = (t >= d) ? s[t - d] : 0;
        __syncthreads();
        s[t] += u;
        __syncthreads();
    }
    if (i < NN) tmp[i] = s[t];
    if (t == 1023) g_bsum[a][bx] = s[t];
    __threadfence();
    if (t == 0) amLast = (atomicAdd(&g_c1, 1) == 2 * NB - 1);
    __syncthreads();
    if (amLast) {
        // scan of the 2x49 block sums
        int aa = t >> 6, j = t & 63;
        int val = (t < 128 && j < NB) ? g_bsum[aa][j] : 0;
        s[t] = val;
        __syncthreads();
#pragma unroll
        for (int d = 1; d < 64; d <<= 1) {
            int u = (t < 128 && j >= d) ? s[t - d] : 0;
            __syncthreads();
            if (t < 128) s[t] += u;
            __syncthreads();
        }
        if (t < 128 && j < NB) g_bsum[aa][j] = s[t] - val;   // exclusive base
        __syncthreads();
        if (t == 0) { __threadfence(); g_flag1 = 1; }
    }
    while (*(volatile int*)&g_flag1 == 0) {}
    __threadfence();

    // phase 2: final offsets
    if (i < NN) {
        int excl = tmp[i] - deg[i] + g_bsum[a][bx];
        off[i] = excl;
        tmp[i] = excl;   // cur = excl
    }
    if (i == 0) off[NN] = EE;
    __threadfence();
    if (t == 0) {
        if (atomicAdd(&g_c2, 1) == 2 * NB - 1) { __threadfence(); g_flag2 = 1; }
    }
    while (*(volatile int*)&g_flag2 == 0) {}
    __threadfence();

    // phase 3: scatter (all 98 blocks, 4-edge batching for atomic MLP)
    int gid = (a * NB + bx) * 1024 + t;
    int stride = 2 * NB * 1024;
    int e = gid;
    for (; e + 3 * stride < EE; e += 4 * stride) {
        int e0 = e, e1 = e + stride, e2 = e + 2 * stride, e3 = e + 3 * stride;
        int s0 = srcA[e0], s1 = srcA[e1], s2 = srcA[e2], s3 = srcA[e3];
        int d0 = dstA[e0], d1 = dstA[e1], d2 = dstA[e2], d3 = dstA[e3];
        int ps0 = atomicAdd(&g_cur_s[s0], 1);
        int ps1 = atomicAdd(&g_cur_s[s1], 1);
        int ps2 = atomicAdd(&g_cur_s[s2], 1);
        int ps3 = atomicAdd(&g_cur_s[s3], 1);
        int pd0 = atomicAdd(&g_cur_d[d0], 1);
        int pd1 = atomicAdd(&g_cur_d[d1], 1);
        int pd2 = atomicAdd(&g_cur_d[d2], 1);
        int pd3 = atomicAdd(&g_cur_d[d3], 1);
        g_csr_s_dst[ps0] = d0;
        g_csr_s_dst[ps1] = d1;
        g_csr_s_dst[ps2] = d2;
        g_csr_s_dst[ps3] = d3;
        g_csr_d[pd0] = make_int2(s0, ps0);
        g_csr_d[pd1] = make_int2(s1, ps1);
        g_csr_d[pd2] = make_int2(s2, ps2);
        g_csr_d[pd3] = make_int2(s3, ps3);
    }
    for (; e < EE; e += stride) {
        int sv = srcA[e], dv = dstA[e];
        int ps = atomicAdd(&g_cur_s[sv], 1);
        g_csr_s_dst[ps] = dv;
        int pd = atomicAdd(&g_cur_d[dv], 1);
        g_csr_d[pd] = make_int2(sv, ps);
    }
}

// =======================================================================
// pass 1 (CSR by src): warp per src node, Q (fp32) in regs, 8-edge unroll,
// K gathered as fp16 (8B/lane). ev at CSR-s slot; rnorm per (node,head).
// =======================================================================
__global__ void __launch_bounds__(256) k_edge_scores()
{
    int gwarp  = (blockIdx.x * blockDim.x + threadIdx.x) >> 5;
    int nwarps = (gridDim.x * blockDim.x) >> 5;
    int lane   = threadIdx.x & 31;
    const bool leader = (lane & 7) == 0;
    const int h = lane >> 3;
    const uint2* Kb = (const uint2*)g_Kh;   // 32 uint2 per row
    for (int n = gwarp; n < NN; n += nwarps) {
        int beg = g_off_s[n];
        int end = g_off_s[n + 1];
        if (beg == end) continue;
        float4 qv = __ldg((const float4*)(g_Q + (size_t)n * DD + lane * 4));
        float ls = 0.f;
        int p = beg;
        for (; p + 8 <= end; p += 8) {
            int dd[8];
#pragma unroll
            for (int j = 0; j < 8; j++) dd[j] = __ldg(&g_csr_s_dst[p + j]);
            uint2 ku[8];
#pragma unroll
            for (int j = 0; j < 8; j++)
                ku[j] = __ldg(&Kb[(size_t)dd[j] * 32 + lane]);
            float aa[8];
#pragma unroll
            for (int j = 0; j < 8; j++) {
                float2 f0 = __half22float2(*(const __half2*)&ku[j].x);
                float2 f1 = __half22float2(*(const __half2*)&ku[j].y);
                aa[j] = qv.x * f0.x + qv.y * f0.y + qv.z * f1.x + qv.w * f1.y;
            }
#pragma unroll
            for (int m = 1; m <= 4; m <<= 1)
#pragma unroll
                for (int j = 0; j < 8; j++)
                    aa[j] += __shfl_xor_sync(0xffffffffu, aa[j], m);
            if (leader) {
#pragma unroll
                for (int j = 0; j < 8; j++) {
                    float ev = __expf(aa[j]);   // scores O(1): max-shift unnecessary
                    g_ev[(size_t)(p + j) * HH + h] = ev;
                    ls += ev;
                }
            }
        }
        for (; p < end; p++) {
            int d0 = __ldg(&g_csr_s_dst[p]);
            uint2 ku = __ldg(&Kb[(size_t)d0 * 32 + lane]);
            float2 f0 = __half22float2(*(const __half2*)&ku.x);
            float2 f1 = __half22float2(*(const __half2*)&ku.y);
            float a0 = qv.x * f0.x + qv.y * f0.y + qv.z * f1.x + qv.w * f1.y;
#pragma unroll
            for (int m = 1; m <= 4; m <<= 1)
                a0 += __shfl_xor_sync(0xffffffffu, a0, m);
            float e0 = __expf(a0);
            if (leader) {
                g_ev[(size_t)p * HH + h] = e0;
                ls += e0;
            }
        }
        if (leader)
            g_rnorm[n * HH + h] = (float)(end - beg) / ls;
    }
}

// =======================================================================
// pass 2 (CSR by dst): warp per dst node, 8-edge unroll, M fp16 gathers,
// fp32 accumulate, one coalesced store.
// =======================================================================
__global__ void __launch_bounds__(256) k_aggregate()
{
    int gwarp  = (blockIdx.x * blockDim.x + threadIdx.x) >> 5;
    int nwarps = (gridDim.x * blockDim.x) >> 5;
    int lane   = threadIdx.x & 31;
    const int h = lane >> 3;
    const uint2* Mb = (const uint2*)g_Mh;   // 32 uint2 per row
    for (int n = gwarp; n < NN; n += nwarps) {
        int beg = g_off_d[n];
        int end = g_off_d[n + 1];
        float4 acc = make_float4(0.f, 0.f, 0.f, 0.f);
        int e = beg;
        for (; e + 8 <= end; e += 8) {
            int2 cc[8];
#pragma unroll
            for (int j = 0; j < 8; j++) cc[j] = __ldg(&g_csr_d[e + j]);
            float al[8];
#pragma unroll
            for (int j = 0; j < 8; j++)
                al[j] = __ldg(&g_ev[(size_t)cc[j].y * HH + h]) *
                        __ldg(&g_rnorm[cc[j].x * HH + h]);
            uint2 mu[8];
#pragma unroll
            for (int j = 0; j < 8; j++)
                mu[j] = __ldg(&Mb[(size_t)cc[j].x * 32 + lane]);
#pragma unroll
            for (int j = 0; j < 8; j++) {
                float2 f0 = __half22float2(*(const __half2*)&mu[j].x);
                float2 f1 = __half22float2(*(const __half2*)&mu[j].y);
                acc.x += f0.x * al[j];
                acc.y += f0.y * al[j];
                acc.z += f1.x * al[j];
                acc.w += f1.y * al[j];
            }
        }
        for (; e < end; e++) {
            int2 c0 = __ldg(&g_csr_d[e]);
            float al0 = __ldg(&g_ev[(size_t)c0.y * HH + h]) * __ldg(&g_rnorm[c0.x * HH + h]);
            uint2 mu = __ldg(&Mb[(size_t)c0.x * 32 + lane]);
            float2 f0 = __half22float2(*(const __half2*)&mu.x);
            float2 f1 = __half22float2(*(const __half2*)&mu.y);
            acc.x += f0.x * al0;
            acc.y += f0.y * al0;
            acc.z += f1.x * al0;
            acc.w += f1.y * al0;
        }
        *(float4*)(g_out + (size_t)n * DD + lane * 4) = acc;
    }
}

// =======================================================================
// launcher
// =======================================================================
extern "C" void kernel_launch(void* const* d_in, const int* in_sizes, int n_in,
                              void* d_out, int out_size)
{
    const float* x     = (const float*)d_in[0];
    const void*  ei    = d_in[1];
    const float* Wk    = (const float*)d_in[2];
    const float* bk    = (const float*)d_in[3];
    const float* Wm    = (const float*)d_in[4];
    const float* bm    = (const float*)d_in[5];
    const float* Wq    = (const float*)d_in[6];
    const float* bq    = (const float*)d_in[7];
    const float* W1    = (const float*)d_in[8];
    const float* b1    = (const float*)d_in[9];
    const float* gamma = (const float*)d_in[10];
    const float* beta  = (const float*)d_in[11];
    const float* W2    = (const float*)d_in[12];
    const float* b2    = (const float*)d_in[13];
    float* out = (float*)d_out;

    // temp src/dst live in g_ev (pass1 writes g_ev only after scatter done)
    int* srcTmp = (int*)g_ev;
    int* dstTmp = ((int*)g_ev) + EE;

    cudaFuncSetAttribute(k_proj_convert, cudaFuncAttributeMaxDynamicSharedMemorySize, DSMEM);
    cudaFuncSetAttribute(k_gemm_mlp1,    cudaFuncAttributeMaxDynamicSharedMemorySize, DSMEM);
    cudaFuncSetAttribute(k_gemm_mlp2,    cudaFuncAttributeMaxDynamicSharedMemorySize, DSMEM);

    k_init<<<128, 256>>>((const unsigned long long*)ei);
    k_proj_convert<<<3 * ROWT + CONVB, 256, DSMEM>>>(x, Wk, bk, Wm, bm, Wq, bq,
                                                     ei, srcTmp, dstTmp);
    k_build<<<dim3(NB, 2), 1024>>>(srcTmp, dstTmp);
    k_edge_scores<<<2048, 256>>>();
    k_aggregate<<<2048, 256>>>();
    k_gemm_mlp1<<<ROWT, 256, DSMEM>>>(W1, b1, gamma, beta);
    k_gemm_mlp2<<<ROWT, 256, DSMEM>>>(W2, b2, out);
}

// round 13
// speedup vs baseline: 1.0795x; 1.0795x over previous
#include <cuda_runtime.h>
#include <cuda_fp16.h>
#include <cstdint>

#define NN 50000
#define EE 800000
#define DD 128
#define HH 4
#define NB 49          // scan blocks per array: 49*1024 >= NN
#define ROWT 391       // (NN+127)/128
#define CONVB 512      // convert blocks inside the fused proj launch

// ---- scratch (device globals; no allocation allowed) ----
__device__ unsigned g_Kh[NN * 64];   // K rows as 64 half2 (fp16)
__device__ unsigned g_Mh[NN * 64];   // M rows as 64 half2 (fp16)
__device__ float g_Q[NN * DD];
__device__ float g_ev[EE * HH];      // also reused as int scratch pre-pass1
__device__ float g_rnorm[NN * HH];
__device__ float g_out[NN * DD];
__device__ float g_h[NN * DD];
__device__ float g_colsum[DD];
__device__ float g_colsumsq[DD];
__device__ float g_scale[DD];
__device__ float g_shift[DD];
__device__ int   g_is64;
__device__ int   g_ctr;
__device__ int   g_ctrA;

// CSR structures
__device__ int  g_deg_s[NN];
__device__ int  g_deg_d[NN];
__device__ int  g_off_s[NN + 1];
__device__ int  g_off_d[NN + 1];
__device__ int  g_cur_s[NN];     // also inclusive-scan temp
__device__ int  g_cur_d[NN];
__device__ int  g_bsum[2][64];
__device__ int  g_csr_s_dst[EE];     // dst per src-sorted slot
__device__ int2 g_csr_d[EE];         // (src, src_slot) per dst-sorted slot

// =======================================================================
// init + dtype probe. Reference asks int64 but JAX x64-disabled silently
// yields int32; first-2048-u64 all < NN only if genuinely int64.
// =======================================================================
__global__ void k_init(const unsigned long long* __restrict__ p)
{
    int i = blockIdx.x * blockDim.x + threadIdx.x;
    int stride = gridDim.x * blockDim.x;
    for (int j = i; j < NN; j += stride) { g_deg_s[j] = 0; g_deg_d[j] = 0; }
    if (i < DD) { g_colsum[i] = 0.f; g_colsumsq[i] = 0.f; }
    if (i == 0) { g_ctr = 0; g_ctrA = 0; }
    if (blockIdx.x == 0) {
        __shared__ int ok;
        if (threadIdx.x == 0) ok = 1;
        __syncthreads();
        bool bad = false;
#pragma unroll
        for (int j = 0; j < 8; j++)
            if (p[threadIdx.x * 8 + j] >= (unsigned long long)NN) bad = true;
        if (bad) atomicExch(&ok, 0);
        __syncthreads();
        if (threadIdx.x == 0) g_is64 = ok;
    }
}

// =======================================================================
// tf32 tensor-core GEMM body: 128x128 tile, BK=32, m16n8k8, static smem.
// BN=true: fused BatchNorm+ReLU on A load.
// STATS=true: per-column sum/sumsq of output + last-block BN finalize.
// HOUT=true: emit fp16 (half2-packed) output rows instead of fp32.
// =======================================================================
#define AS_STRIDE 36
#define WS_STRIDE 136

__device__ __forceinline__ uint32_t f2tf(float x)
{
    uint32_t r;
    asm("cvt.rna.tf32.f32 %0, %1;" : "=r"(r) : "f"(x));
    return r;
}

__device__ __forceinline__ void mma_tf32(float* c, const uint32_t* a, const uint32_t* b)
{
    asm volatile(
        "mma.sync.aligned.m16n8k8.row.col.f32.tf32.tf32.f32 "
        "{%0,%1,%2,%3}, {%4,%5,%6,%7}, {%8,%9}, {%0,%1,%2,%3};"
        : "+f"(c[0]), "+f"(c[1]), "+f"(c[2]), "+f"(c[3])
        : "r"(a[0]), "r"(a[1]), "r"(a[2]), "r"(a[3]), "r"(b[0]), "r"(b[1]));
}

template <bool BN, bool STATS, bool HOUT>
__device__ __forceinline__ void gemm_body(
    int rowBase,
    const float* __restrict__ A, const float* __restrict__ W,
    const float* __restrict__ bias, float* __restrict__ C,
    unsigned* __restrict__ Ch, float outScale,
    const float* __restrict__ gamma, const float* __restrict__ beta,
    int nblocks)
{
    __shared__ uint32_t As[128 * AS_STRIDE];
    __shared__ uint32_t Ws[32 * WS_STRIDE];
    __shared__ float2 red[4 * 128];

    const int tid = threadIdx.x;
    const int wid = tid >> 5;
    const int lane = tid & 31;
    const int g = lane >> 2;
    const int q = lane & 3;
    const int warpM = wid & 3;
    const int warpN = wid >> 2;

    float acc[2][8][4];
#pragma unroll
    for (int mt = 0; mt < 2; mt++)
#pragma unroll
        for (int nt = 0; nt < 8; nt++)
#pragma unroll
            for (int r = 0; r < 4; r++) acc[mt][nt][r] = 0.f;

    for (int kc = 0; kc < DD; kc += 32) {
#pragma unroll
        for (int it = 0; it < 4; it++) {
            int idx = tid + it * 256;
            int r   = idx >> 3;
            int c4  = idx & 7;
            int grow = rowBase + r;
            float4 v = make_float4(0.f, 0.f, 0.f, 0.f);
            if (grow < NN) v = *(const float4*)(A + (size_t)grow * DD + kc + c4 * 4);
            if (BN) {
                int cb = kc + c4 * 4;
                v.x = fmaxf(v.x * g_scale[cb + 0] + g_shift[cb + 0], 0.f);
                v.y = fmaxf(v.y * g_scale[cb + 1] + g_shift[cb + 1], 0.f);
                v.z = fmaxf(v.z * g_scale[cb + 2] + g_shift[cb + 2], 0.f);
                v.w = fmaxf(v.w * g_scale[cb + 3] + g_shift[cb + 3], 0.f);
            }
            uint4 t = make_uint4(f2tf(v.x), f2tf(v.y), f2tf(v.z), f2tf(v.w));
            *(uint4*)&As[r * AS_STRIDE + c4 * 4] = t;
        }
#pragma unroll
        for (int it = 0; it < 4; it++) {
            int idx = tid + it * 256;
            int r   = idx >> 5;
            int c4  = idx & 31;
            float4 v = *(const float4*)(W + (size_t)(kc + r) * DD + c4 * 4);
            uint4 t = make_uint4(f2tf(v.x), f2tf(v.y), f2tf(v.z), f2tf(v.w));
            *(uint4*)&Ws[r * WS_STRIDE + c4 * 4] = t;
        }
        __syncthreads();

#pragma unroll
        for (int ks = 0; ks < 4; ks++) {
            const int k = ks * 8;
            uint32_t a[2][4];
#pragma unroll
            for (int mt = 0; mt < 2; mt++) {
                int Rm = warpM * 32 + mt * 16;
                a[mt][0] = As[(Rm + g)     * AS_STRIDE + k + q];
                a[mt][1] = As[(Rm + g + 8) * AS_STRIDE + k + q];
                a[mt][2] = As[(Rm + g)     * AS_STRIDE + k + q + 4];
                a[mt][3] = As[(Rm + g + 8) * AS_STRIDE + k + q + 4];
            }
            uint32_t b[8][2];
#pragma unroll
            for (int nt = 0; nt < 8; nt++) {
                int col = warpN * 64 + nt * 8 + g;
                b[nt][0] = Ws[(k + q)     * WS_STRIDE + col];
                b[nt][1] = Ws[(k + q + 4) * WS_STRIDE + col];
            }
#pragma unroll
            for (int mt = 0; mt < 2; mt++)
#pragma unroll
                for (int nt = 0; nt < 8; nt++)
                    mma_tf32(acc[mt][nt], a[mt], b[nt]);
        }
        __syncthreads();
    }

#pragma unroll
    for (int nt = 0; nt < 8; nt++) {
        int col = warpN * 64 + nt * 8 + 2 * q;
        float bb0 = bias[col], bb1 = bias[col + 1];
        float cs0 = 0.f, cs1 = 0.f, cq0 = 0.f, cq1 = 0.f;
#pragma unroll
        for (int mt = 0; mt < 2; mt++) {
            int r0 = rowBase + warpM * 32 + mt * 16 + g;
            if (r0 < NN) {
                float o0 = (acc[mt][nt][0] + bb0) * outScale;
                float o1 = (acc[mt][nt][1] + bb1) * outScale;
                if (HOUT) {
                    __half2 hh = __floats2half2_rn(o0, o1);
                    Ch[(size_t)r0 * 64 + (col >> 1)] = *(unsigned*)&hh;
                } else {
                    *(float2*)(C + (size_t)r0 * DD + col) = make_float2(o0, o1);
                }
                if (STATS) { cs0 += o0; cq0 += o0 * o0; cs1 += o1; cq1 += o1 * o1; }
            }
            int r1 = r0 + 8;
            if (r1 < NN) {
                float o2 = (acc[mt][nt][2] + bb0) * outScale;
                float o3 = (acc[mt][nt][3] + bb1) * outScale;
                if (HOUT) {
                    __half2 hh = __floats2half2_rn(o2, o3);
                    Ch[(size_t)r1 * 64 + (col >> 1)] = *(unsigned*)&hh;
                } else {
                    *(float2*)(C + (size_t)r1 * DD + col) = make_float2(o2, o3);
                }
                if (STATS) { cs0 += o2; cq0 += o2 * o2; cs1 += o3; cq1 += o3 * o3; }
            }
        }
        if (STATS) {
#pragma unroll
            for (int mask = 4; mask <= 16; mask <<= 1) {
                cs0 += __shfl_xor_sync(0xffffffffu, cs0, mask);
                cq0 += __shfl_xor_sync(0xffffffffu, cq0, mask);
                cs1 += __shfl_xor_sync(0xffffffffu, cs1, mask);
                cq1 += __shfl_xor_sync(0xffffffffu, cq1, mask);
            }
            if (g == 0) {
                red[warpM * 128 + col]     = make_float2(cs0, cq0);
                red[warpM * 128 + col + 1] = make_float2(cs1, cq1);
            }
        }
    }

    if (STATS) {
        __syncthreads();
        if (tid < 128) {
            float a = 0.f, b = 0.f;
#pragma unroll
            for (int r = 0; r < 4; r++) {
                float2 v = red[r * 128 + tid];
                a += v.x; b += v.y;
            }
            atomicAdd(&g_colsum[tid], a);
            atomicAdd(&g_colsumsq[tid], b);
        }
        __threadfence();
        __syncthreads();
        __shared__ int amLast;
        if (tid == 0)
            amLast = (atomicAdd(&g_ctr, 1) == nblocks - 1);
        __syncthreads();
        if (amLast && tid < 128) {
            int c = tid;
            float invN = 1.0f / (float)NN;
            float mean = g_colsum[c] * invN;
            float var  = g_colsumsq[c] * invN - mean * mean;
            float rstd = rsqrtf(var + 1e-5f);
            float sc = rstd * gamma[c];
            g_scale[c] = sc;
            g_shift[c] = beta[c] - mean * sc;
        }
    }
}

// =======================================================================
// fused launch: blocks [0, CONVB) run edge-index convert + histograms,
// blocks [CONVB, CONVB+3*ROWT) run the 3 projection GEMMs.
// K and M are emitted as fp16 (gather operands); Q stays fp32.
// =======================================================================
__global__ void __launch_bounds__(256, 2) k_proj_convert(
    const float* __restrict__ x,
    const float* __restrict__ Wk, const float* __restrict__ bk,
    const float* __restrict__ Wm, const float* __restrict__ bm,
    const float* __restrict__ Wq, const float* __restrict__ bq,
    const void* __restrict__ raw,
    int* __restrict__ srcA, int* __restrict__ dstA)
{
    if (blockIdx.x < CONVB) {
        const long long* e64 = (const long long*)raw;
        const int*       e32 = (const int*)raw;
        const int is64 = g_is64;
        int i = blockIdx.x * 256 + threadIdx.x;
        int stride = CONVB * 256;
        for (int e = i; e < EE; e += stride) {
            int s, d;
            if (is64) { s = (int)e64[e]; d = (int)e64[EE + e]; }
            else      { s = e32[e];      d = e32[EE + e]; }
            srcA[e] = s; dstA[e] = d;
            atomicAdd(&g_deg_s[s], 1);
            atomicAdd(&g_deg_d[d], 1);
        }
    } else {
        int gb = blockIdx.x - CONVB;
        int by = gb / ROWT;
        int bx = gb - by * ROWT;
        if (by == 0)
            gemm_body<false, false, true>(bx * 128, x, Wk, bk, nullptr, g_Kh, 1.f,
                                          nullptr, nullptr, 0);
        else if (by == 1)
            gemm_body<false, false, true>(bx * 128, x, Wm, bm, nullptr, g_Mh, 1.f,
                                          nullptr, nullptr, 0);
        else
            gemm_body<false, false, false>(bx * 128, x, Wq, bq, g_Q, nullptr,
                                           0.17677669529663687f, nullptr, nullptr, 0); // 1/sqrt(32)
    }
}

__global__ void __launch_bounds__(256, 2) k_gemm_mlp1(
    const float* __restrict__ W1, const float* __restrict__ b1,
    const float* __restrict__ gamma, const float* __restrict__ beta)
{
    gemm_body<false, true, false>(blockIdx.x * 128, g_out, W1, b1, g_h, nullptr,
                                  1.f, gamma, beta, ROWT);
}

__global__ void __launch_bounds__(256, 2) k_gemm_mlp2(
    const float* __restrict__ W2, const float* __restrict__ b2,
    float* __restrict__ outp)
{
    gemm_body<true, false, false>(blockIdx.x * 128, g_h, W2, b2, outp, nullptr,
                                  1.f, nullptr, nullptr, 0);
}

// ---- chip-wide scan, phase A (block scans) + fused phase B (last block) ----
__global__ void __launch_bounds__(1024) k_scanA()
{
    const int a = blockIdx.y;
    const int* deg = a ? g_deg_d : g_deg_s;
    int* tmp = a ? g_cur_d : g_cur_s;
    __shared__ int s[1024];
    int t = threadIdx.x;
    int i = blockIdx.x * 1024 + t;
    int v = (i < NN) ? deg[i] : 0;
    s[t] = v;
    __syncthreads();
#pragma unroll
    for (int d = 1; d < 1024; d <<= 1) {
        int u = (t >= d) ? s[t - d] : 0;
        __syncthreads();
        s[t] += u;
        __syncthreads();
    }
    if (i < NN) tmp[i] = s[t];
    if (t == 1023) g_bsum[a][blockIdx.x] = s[t];

    __threadfence();
    __syncthreads();
    __shared__ int amLast;
    if (t == 0) amLast = (atomicAdd(&g_ctrA, 1) == 2 * NB - 1);
    __syncthreads();
    if (amLast) {
        int aa = t >> 6, j = t & 63;
        int val = (t < 128 && j < NB) ? g_bsum[aa][j] : 0;
        s[t] = val;
        __syncthreads();
#pragma unroll
        for (int d = 1; d < 64; d <<= 1) {
            int u = (t < 128 && j >= d) ? s[t - d] : 0;
            __syncthreads();
            if (t < 128) s[t] += u;
            __syncthreads();
        }
        if (t < 128 && j < NB) g_bsum[aa][j] = s[t] - val;  // exclusive base
    }
}

__global__ void __launch_bounds__(1024) k_scanC()
{
    const int a = blockIdx.y;
    const int* deg = a ? g_deg_d : g_deg_s;
    int* tmp = a ? g_cur_d : g_cur_s;
    int* off = a ? g_off_d : g_off_s;
    int i = blockIdx.x * 1024 + threadIdx.x;
    if (i < NN) {
        int excl = tmp[i] - deg[i] + g_bsum[a][blockIdx.x];
        off[i] = excl;
        tmp[i] = excl;   // cur = excl
    }
    if (i == 0) off[NN] = EE;
}

// scatter: src-CSR gets dst; dst-CSR gets (src, src_slot) cross-link.
// 4-edge batching raises atomic MLP (318-cyc ATOMG latency each).
__global__ void k_scatter(const int* __restrict__ srcA, const int* __restrict__ dstA)
{
    int i = blockIdx.x * blockDim.x + threadIdx.x;
    int stride = gridDim.x * blockDim.x;
    int e = i;
    for (; e + 3 * stride < EE; e += 4 * stride) {
        int e0 = e, e1 = e + stride, e2 = e + 2 * stride, e3 = e + 3 * stride;
        int s0 = srcA[e0], s1 = srcA[e1], s2 = srcA[e2], s3 = srcA[e3];
        int d0 = dstA[e0], d1 = dstA[e1], d2 = dstA[e2], d3 = dstA[e3];
        int ps0 = atomicAdd(&g_cur_s[s0], 1);
        int ps1 = atomicAdd(&g_cur_s[s1], 1);
        int ps2 = atomicAdd(&g_cur_s[s2], 1);
        int ps3 = atomicAdd(&g_cur_s[s3], 1);
        int pd0 = atomicAdd(&g_cur_d[d0], 1);
        int pd1 = atomicAdd(&g_cur_d[d1], 1);
        int pd2 = atomicAdd(&g_cur_d[d2], 1);
        int pd3 = atomicAdd(&g_cur_d[d3], 1);
        g_csr_s_dst[ps0] = d0;
        g_csr_s_dst[ps1] = d1;
        g_csr_s_dst[ps2] = d2;
        g_csr_s_dst[ps3] = d3;
        g_csr_d[pd0] = make_int2(s0, ps0);
        g_csr_d[pd1] = make_int2(s1, ps1);
        g_csr_d[pd2] = make_int2(s2, ps2);
        g_csr_d[pd3] = make_int2(s3, ps3);
    }
    for (; e < EE; e += stride) {
        int s = srcA[e], d = dstA[e];
        int ps = atomicAdd(&g_cur_s[s], 1);
        g_csr_s_dst[ps] = d;
        int pd = atomicAdd(&g_cur_d[d], 1);
        g_csr_d[pd] = make_int2(s, ps);
    }
}

// =======================================================================
// pass 1 (CSR by src): warp per src node, Q as half2 pair in regs,
// 8-edge unroll, K fp16 gathers, half2 dot (hmul2+hfma2), fp32 reduce.
// =======================================================================
__global__ void __launch_bounds__(256) k_edge_scores()
{
    int gwarp  = (blockIdx.x * blockDim.x + threadIdx.x) >> 5;
    int nwarps = (gridDim.x * blockDim.x) >> 5;
    int lane   = threadIdx.x & 31;
    const bool leader = (lane & 7) == 0;
    const int h = lane >> 3;
    const uint2* Kb = (const uint2*)g_Kh;   // 32 uint2 per row
    for (int n = gwarp; n < NN; n += nwarps) {
        int beg = g_off_s[n];
        int end = g_off_s[n + 1];
        if (beg == end) continue;
        float4 qv = __ldg((const float4*)(g_Q + (size_t)n * DD + lane * 4));
        const __half2 qa = __floats2half2_rn(qv.x, qv.y);
        const __half2 qb = __floats2half2_rn(qv.z, qv.w);
        float ls = 0.f;
        int p = beg;
        for (; p + 8 <= end; p += 8) {
            int dd[8];
#pragma unroll
            for (int j = 0; j < 8; j++) dd[j] = __ldg(&g_csr_s_dst[p + j]);
            uint2 ku[8];
#pragma unroll
            for (int j = 0; j < 8; j++)
                ku[j] = __ldg(&Kb[(size_t)dd[j] * 32 + lane]);
            float aa[8];
#pragma unroll
            for (int j = 0; j < 8; j++) {
                __half2 pr = __hfma2(qa, *(const __half2*)&ku[j].x,
                                     __hmul2(qb, *(const __half2*)&ku[j].y));
                float2 f = __half22float2(pr);
                aa[j] = f.x + f.y;
            }
#pragma unroll
            for (int m = 1; m <= 4; m <<= 1)
#pragma unroll
                for (int j = 0; j < 8; j++)
                    aa[j] += __shfl_xor_sync(0xffffffffu, aa[j], m);
            if (leader) {
#pragma unroll
                for (int j = 0; j < 8; j++) {
                    float ev = __expf(aa[j]);   // scores O(1): max-shift unnecessary
                    g_ev[(size_t)(p + j) * HH + h] = ev;
                    ls += ev;
                }
            }
        }
        for (; p < end; p++) {
            int d0 = __ldg(&g_csr_s_dst[p]);
            uint2 ku = __ldg(&Kb[(size_t)d0 * 32 + lane]);
            __half2 pr = __hfma2(qa, *(const __half2*)&ku.x,
                                 __hmul2(qb, *(const __half2*)&ku.y));
            float2 f = __half22float2(pr);
            float a0 = f.x + f.y;
#pragma unroll
            for (int m = 1; m <= 4; m <<= 1)
                a0 += __shfl_xor_sync(0xffffffffu, a0, m);
            float e0 = __expf(a0);
            if (leader) {
                g_ev[(size_t)p * HH + h] = e0;
                ls += e0;
            }
        }
        if (leader)
            g_rnorm[n * HH + h] = (float)(end - beg) / ls;
    }
}

// =======================================================================
// pass 2 (CSR by dst): warp per dst node, 8-edge unroll, M fp16 gathers,
// fp32 accumulate, one coalesced store.
// =======================================================================
__global__ void __launch_bounds__(256) k_aggregate()
{
    int gwarp  = (blockIdx.x * blockDim.x + threadIdx.x) >> 5;
    int nwarps = (gridDim.x * blockDim.x) >> 5;
    int lane   = threadIdx.x & 31;
    const int h = lane >> 3;
    const uint2* Mb = (const uint2*)g_Mh;   // 32 uint2 per row
    for (int n = gwarp; n < NN; n += nwarps) {
        int beg = g_off_d[n];
        int end = g_off_d[n + 1];
        float4 acc = make_float4(0.f, 0.f, 0.f, 0.f);
        int e = beg;
        for (; e + 8 <= end; e += 8) {
            int2 cc[8];
#pragma unroll
            for (int j = 0; j < 8; j++) cc[j] = __ldg(&g_csr_d[e + j]);
            float al[8];
#pragma unroll
            for (int j = 0; j < 8; j++)
                al[j] = __ldg(&g_ev[(size_t)cc[j].y * HH + h]) *
                        __ldg(&g_rnorm[cc[j].x * HH + h]);
            uint2 mu[8];
#pragma unroll
            for (int j = 0; j < 8; j++)
                mu[j] = __ldg(&Mb[(size_t)cc[j].x * 32 + lane]);
#pragma unroll
            for (int j = 0; j < 8; j++) {
                float2 f0 = __half22float2(*(const __half2*)&mu[j].x);
                float2 f1 = __half22float2(*(const __half2*)&mu[j].y);
                acc.x += f0.x * al[j];
                acc.y += f0.y * al[j];
                acc.z += f1.x * al[j];
                acc.w += f1.y * al[j];
            }
        }
        for (; e < end; e++) {
            int2 c0 = __ldg(&g_csr_d[e]);
            float al0 = __ldg(&g_ev[(size_t)c0.y * HH + h]) * __ldg(&g_rnorm[c0.x * HH + h]);
            uint2 mu = __ldg(&Mb[(size_t)c0.x * 32 + lane]);
            float2 f0 = __half22float2(*(const __half2*)&mu.x);
            float2 f1 = __half22float2(*(const __half2*)&mu.y);
            acc.x += f0.x * al0;
            acc.y += f0.y * al0;
            acc.z += f1.x * al0;
            acc.w += f1.y * al0;
        }
        *(float4*)(g_out + (size_t)n * DD + lane * 4) = acc;
    }
}

// =======================================================================
// launcher
// =======================================================================
extern "C" void kernel_launch(void* const* d_in, const int* in_sizes, int n_in,
                              void* d_out, int out_size)
{
    const float* x     = (const float*)d_in[0];
    const void*  ei    = d_in[1];
    const float* Wk    = (const float*)d_in[2];
    const float* bk    = (const float*)d_in[3];
    const float* Wm    = (const float*)d_in[4];
    const float* bm    = (const float*)d_in[5];
    const float* Wq    = (const float*)d_in[6];
    const float* bq    = (const float*)d_in[7];
    const float* W1    = (const float*)d_in[8];
    const float* b1    = (const float*)d_in[9];
    const float* gamma = (const float*)d_in[10];
    const float* beta  = (const float*)d_in[11];
    const float* W2    = (const float*)d_in[12];
    const float* b2    = (const float*)d_in[13];
    float* out = (float*)d_out;

    // temp src/dst live in g_ev (pass1 writes g_ev only after scatter done)
    int* srcTmp = (int*)g_ev;
    int* dstTmp = ((int*)g_ev) + EE;

    k_init<<<128, 256>>>((const unsigned long long*)ei);
    k_proj_convert<<<3 * ROWT + CONVB, 256>>>(x, Wk, bk, Wm, bm, Wq, bq,
                                              ei, srcTmp, dstTmp);
    k_scanA<<<dim3(NB, 2), 1024>>>();
    k_scanC<<<dim3(NB, 2), 1024>>>();
    k_scatter<<<512, 256>>>(srcTmp, dstTmp);
    k_edge_scores<<<2048, 256>>>();
    k_aggregate<<<2048, 256>>>();
    k_gemm_mlp1<<<ROWT, 256>>>(W1, b1, gamma, beta);
    k_gemm_mlp2<<<ROWT, 256>>>(W2, b2, out);
}